// round 14
// baseline (speedup 1.0000x reference)
#include <cuda_runtime.h>

#define NPIX 4096
#define CDIM 64
#define KSTR 68   // padded smem row stride (floats)

// -------- scratch (device globals: allocation-free) --------
__device__ float g_q[4 * NPIX * CDIM];
__device__ float g_k[4 * NPIX * CDIM];
__device__ float g_v[4 * NPIX * CDIM];

// -------- helpers --------
__device__ __forceinline__ float tf32r(float x) {
    unsigned int u;
    asm("cvt.rna.tf32.f32 %0, %1;" : "=r"(u) : "f"(x));
    return __uint_as_float(u);
}
__device__ __forceinline__ unsigned int fbits(float x) { return __float_as_uint(x); }

// D += A(16x8,row) * B(8x8,col)  tf32, fp32 accum
__device__ __forceinline__ void mma_tf32(float* d, const unsigned int* a,
                                         unsigned int b0, unsigned int b1) {
    asm volatile(
        "mma.sync.aligned.m16n8k8.row.col.f32.tf32.tf32.f32 "
        "{%0,%1,%2,%3},{%4,%5,%6,%7},{%8,%9},{%0,%1,%2,%3};\n"
        : "+f"(d[0]), "+f"(d[1]), "+f"(d[2]), "+f"(d[3])
        : "r"(a[0]), "r"(a[1]), "r"(a[2]), "r"(a[3]), "r"(b0), "r"(b1));
}

// ================= projection: q/k/v = W @ x + b, stored as [N,64] =================
__device__ __forceinline__ void proj_one(const float* __restrict__ Xs,
                                         const float* __restrict__ W,
                                         const float* __restrict__ bias,
                                         float* __restrict__ dst, int c, int i0) {
    float acc[32];
    float bb = bias[c];
#pragma unroll
    for (int e = 0; e < 32; e++) acc[e] = bb;
#pragma unroll
    for (int k4 = 0; k4 < 16; k4++) {
        float4 w4 = *(reinterpret_cast<const float4*>(W + c * 64) + k4);
        float ws[4] = {w4.x, w4.y, w4.z, w4.w};
#pragma unroll
        for (int q = 0; q < 4; q++) {
            int cp = k4 * 4 + q;
            float w = ws[q];
#pragma unroll
            for (int e4 = 0; e4 < 8; e4++) {
                float4 xv = *reinterpret_cast<const float4*>(Xs + cp * 64 + i0 + e4 * 4);
                acc[e4 * 4 + 0] = fmaf(w, xv.x, acc[e4 * 4 + 0]);
                acc[e4 * 4 + 1] = fmaf(w, xv.y, acc[e4 * 4 + 1]);
                acc[e4 * 4 + 2] = fmaf(w, xv.z, acc[e4 * 4 + 2]);
                acc[e4 * 4 + 3] = fmaf(w, xv.w, acc[e4 * 4 + 3]);
            }
        }
    }
#pragma unroll
    for (int e = 0; e < 32; e++) dst[(i0 + e) * 64 + c] = tf32r(acc[e]);
}

__global__ void __launch_bounds__(128)
proj_kernel(const float* __restrict__ x1, const float* __restrict__ x2,
            const float* __restrict__ wq, const float* __restrict__ bq,
            const float* __restrict__ wk, const float* __restrict__ bk,
            const float* __restrict__ wv, const float* __restrict__ bv) {
    __shared__ float Xs1[64 * 64];
    __shared__ float Xs2[64 * 64];
    const int b = blockIdx.y;
    const int iBase = blockIdx.x * 64;
    const int tid = threadIdx.x;

    for (int idx = tid; idx < 1024; idx += 128) {
        int r = idx >> 4, c4 = (idx & 15) << 2;
        *reinterpret_cast<float4*>(&Xs1[r * 64 + c4]) =
            *reinterpret_cast<const float4*>(x1 + (size_t)(b * 64 + r) * NPIX + iBase + c4);
        *reinterpret_cast<float4*>(&Xs2[r * 64 + c4]) =
            *reinterpret_cast<const float4*>(x2 + (size_t)(b * 64 + r) * NPIX + iBase + c4);
    }
    __syncthreads();

    const int c = tid & 63;
    const int i0 = (tid >> 6) * 32;
    const size_t dbase = ((size_t)b * NPIX + iBase) * CDIM;
    proj_one(Xs1, wq, bq, g_q + dbase, c, i0);
    proj_one(Xs2, wk, bk, g_k + dbase, c, i0);
    proj_one(Xs2, wv, bv, g_v + dbase, c, i0);
}

// ================= flash attention, BM=BN=64, d=64, tf32 mma =================
__global__ void __launch_bounds__(128)
attn_kernel(const float* __restrict__ x1, const float* __restrict__ gamma_p,
            float* __restrict__ out) {
    extern __shared__ float sm[];
    float* Ks = sm;                  // 64 x KSTR
    float* Vs = sm + 64 * KSTR;      // 64 x KSTR
    float* Ps = sm + 2 * 64 * KSTR;  // 64 x KSTR (Q staging / P / O-transpose)

    const int b = blockIdx.y;
    const int iBase = blockIdx.x * 64;
    const int tid = threadIdx.x;
    const int warp = tid >> 5, lane = tid & 31;
    const int g = lane >> 2, t = lane & 3;
    const int qr = warp * 16 + g;  // this thread's query row (and qr+8)

    const float* Q = g_q + ((size_t)b * NPIX + iBase) * CDIM;
    const float* K = g_k + (size_t)b * NPIX * CDIM;
    const float* V = g_v + (size_t)b * NPIX * CDIM;

    // ---- stage Q tile and build register-resident A fragments ----
    for (int idx = tid; idx < 64 * 16; idx += 128) {
        int r = idx >> 4, c4 = (idx & 15) << 2;
        *reinterpret_cast<float4*>(&Ps[r * KSTR + c4]) =
            *reinterpret_cast<const float4*>(Q + r * 64 + c4);
    }
    __syncthreads();
    unsigned int qf[8][4];
#pragma unroll
    for (int kk = 0; kk < 8; ++kk) {
        qf[kk][0] = fbits(Ps[qr * KSTR + kk * 8 + t]);
        qf[kk][1] = fbits(Ps[(qr + 8) * KSTR + kk * 8 + t]);
        qf[kk][2] = fbits(Ps[qr * KSTR + kk * 8 + t + 4]);
        qf[kk][3] = fbits(Ps[(qr + 8) * KSTR + kk * 8 + t + 4]);
    }

    float oAcc[8][4];
#pragma unroll
    for (int i = 0; i < 8; i++) {
        oAcc[i][0] = 0.f; oAcc[i][1] = 0.f; oAcc[i][2] = 0.f; oAcc[i][3] = 0.f;
    }
    float mA = -1e30f, mB = -1e30f, lA = 0.f, lB = 0.f;

    for (int j0 = 0; j0 < NPIX; j0 += 64) {
        __syncthreads();  // protect Ks/Vs/Ps from previous iteration consumers
        for (int idx = tid; idx < 64 * 16; idx += 128) {
            int r = idx >> 4, c4 = (idx & 15) << 2;
            *reinterpret_cast<float4*>(&Ks[r * KSTR + c4]) =
                *reinterpret_cast<const float4*>(K + (size_t)(j0 + r) * 64 + c4);
            *reinterpret_cast<float4*>(&Vs[r * KSTR + c4]) =
                *reinterpret_cast<const float4*>(V + (size_t)(j0 + r) * 64 + c4);
        }
        __syncthreads();

        // ---- S = Q Ktile^T  (64x64 per block, 16x64 per warp) ----
        float s[8][4];
#pragma unroll
        for (int i = 0; i < 8; i++) {
            s[i][0] = 0.f; s[i][1] = 0.f; s[i][2] = 0.f; s[i][3] = 0.f;
        }
#pragma unroll
        for (int kk = 0; kk < 8; ++kk) {
#pragma unroll
            for (int tn = 0; tn < 8; ++tn) {
                unsigned int b0 = fbits(Ks[(tn * 8 + g) * KSTR + kk * 8 + t]);
                unsigned int b1 = fbits(Ks[(tn * 8 + g) * KSTR + kk * 8 + t + 4]);
                mma_tf32(s[tn], qf[kk], b0, b1);
            }
        }

        // ---- online softmax (rows qr / qr+8, 64 cols spread over 4 lanes) ----
        float tmA = -1e30f, tmB = -1e30f;
#pragma unroll
        for (int tn = 0; tn < 8; ++tn) {
            tmA = fmaxf(tmA, fmaxf(s[tn][0], s[tn][1]));
            tmB = fmaxf(tmB, fmaxf(s[tn][2], s[tn][3]));
        }
        tmA = fmaxf(tmA, __shfl_xor_sync(0xffffffffu, tmA, 1));
        tmA = fmaxf(tmA, __shfl_xor_sync(0xffffffffu, tmA, 2));
        tmB = fmaxf(tmB, __shfl_xor_sync(0xffffffffu, tmB, 1));
        tmB = fmaxf(tmB, __shfl_xor_sync(0xffffffffu, tmB, 2));
        const float mAn = fmaxf(mA, tmA), mBn = fmaxf(mB, tmB);
        const float scA = __expf(mA - mAn), scB = __expf(mB - mBn);
        mA = mAn; mB = mBn;
        float sumA = 0.f, sumB = 0.f;
#pragma unroll
        for (int tn = 0; tn < 8; ++tn) {
            s[tn][0] = __expf(s[tn][0] - mA);
            s[tn][1] = __expf(s[tn][1] - mA);
            s[tn][2] = __expf(s[tn][2] - mB);
            s[tn][3] = __expf(s[tn][3] - mB);
            sumA += s[tn][0] + s[tn][1];
            sumB += s[tn][2] + s[tn][3];
            oAcc[tn][0] *= scA; oAcc[tn][1] *= scA;
            oAcc[tn][2] *= scB; oAcc[tn][3] *= scB;
        }
        sumA += __shfl_xor_sync(0xffffffffu, sumA, 1);
        sumA += __shfl_xor_sync(0xffffffffu, sumA, 2);
        sumB += __shfl_xor_sync(0xffffffffu, sumB, 1);
        sumB += __shfl_xor_sync(0xffffffffu, sumB, 2);
        lA = lA * scA + sumA;
        lB = lB * scB + sumB;

        // ---- write P (warp-private rows) and do O += P Vtile ----
#pragma unroll
        for (int tn = 0; tn < 8; ++tn) {
            int c0 = tn * 8 + 2 * t;
            Ps[qr * KSTR + c0]           = tf32r(s[tn][0]);
            Ps[qr * KSTR + c0 + 1]       = tf32r(s[tn][1]);
            Ps[(qr + 8) * KSTR + c0]     = tf32r(s[tn][2]);
            Ps[(qr + 8) * KSTR + c0 + 1] = tf32r(s[tn][3]);
        }
        __syncwarp();
#pragma unroll
        for (int kk = 0; kk < 8; ++kk) {
            unsigned int a[4];
            a[0] = fbits(Ps[qr * KSTR + kk * 8 + t]);
            a[1] = fbits(Ps[(qr + 8) * KSTR + kk * 8 + t]);
            a[2] = fbits(Ps[qr * KSTR + kk * 8 + t + 4]);
            a[3] = fbits(Ps[(qr + 8) * KSTR + kk * 8 + t + 4]);
#pragma unroll
            for (int tn = 0; tn < 8; ++tn) {
                unsigned int b0 = fbits(Vs[(kk * 8 + t) * KSTR + tn * 8 + g]);
                unsigned int b1 = fbits(Vs[(kk * 8 + t + 4) * KSTR + tn * 8 + g]);
                mma_tf32(oAcc[tn], a, b0, b1);
            }
        }
    }

    // ---- epilogue: O /= l, transpose to [c][i] via smem, coalesced gamma*O + x1 ----
    const float invA = 1.0f / lA;
    const float invB = 1.0f / lB;
    __syncthreads();  // everyone done reading Ps/Vs
#pragma unroll
    for (int tn = 0; tn < 8; ++tn) {
        int c0 = tn * 8 + 2 * t;
        Ps[c0 * KSTR + qr]           = oAcc[tn][0] * invA;
        Ps[(c0 + 1) * KSTR + qr]     = oAcc[tn][1] * invA;
        Ps[c0 * KSTR + qr + 8]       = oAcc[tn][2] * invB;
        Ps[(c0 + 1) * KSTR + qr + 8] = oAcc[tn][3] * invB;
    }
    __syncthreads();
    const float gm = gamma_p[0];
    for (int idx = tid; idx < 64 * 64; idx += 128) {
        int c = idx >> 6, ii = idx & 63;
        size_t gi = ((size_t)(b * CDIM + c)) * NPIX + iBase + ii;
        out[gi] = gm * Ps[c * KSTR + ii] + x1[gi];
    }
}

// ================= launch =================
extern "C" void kernel_launch(void* const* d_in, const int* in_sizes, int n_in,
                              void* d_out, int out_size) {
    const float* x1 = (const float*)d_in[0];
    const float* x2 = (const float*)d_in[1];
    const float* wq = (const float*)d_in[2];
    const float* bq = (const float*)d_in[3];
    const float* wk = (const float*)d_in[4];
    const float* bk = (const float*)d_in[5];
    const float* wv = (const float*)d_in[6];
    const float* bv = (const float*)d_in[7];
    const float* gamma = (const float*)d_in[8];
    float* out = (float*)d_out;

    const int smem_bytes = 3 * 64 * KSTR * (int)sizeof(float);  // 52224
    cudaFuncSetAttribute(attn_kernel, cudaFuncAttributeMaxDynamicSharedMemorySize,
                         smem_bytes);

    dim3 grid(NPIX / 64, 4);
    proj_kernel<<<grid, 128>>>(x1, x2, wq, bq, wk, bk, wv, bv);
    attn_kernel<<<grid, 128, smem_bytes>>>(x1, gamma, out);
}

// round 15
// speedup vs baseline: 2.9861x; 2.9861x over previous
#include <cuda_runtime.h>
#include <cuda_fp16.h>

#define NPIX 4096
#define KH   72                      // half-stride of fragment tiles (144B = 9*16B -> conflict-free)
#define TILE_HALFS (64 * KH)         // 4608 halves
#define WSTR 68                      // proj Wt float stride

// -------- device-global scratch (allocation-free) --------
__device__ __half g_qh[4ull * NPIX * 64];   // [b][n][perm(c)]
__device__ __half g_kh[4ull * NPIX * 64];   // [b][n][perm(c)]
__device__ __half g_vh[4ull * 64 * NPIX];   // [b][c][tile*64 + perm(j_local)]

// fragment permutation: c = kk*16 + 8h + 2t + e  ->  p = t*16 + kk*4 + h*2 + e
__device__ __forceinline__ int perm64(int c) {
    return ((c >> 1) & 3) * 16 + (c >> 4) * 4 + ((c >> 3) & 1) * 2 + (c & 1);
}

// D += A(16x16 f16) * B(16x8 f16), fp32 accum
__device__ __forceinline__ void mma16(float* d, unsigned a0, unsigned a1, unsigned a2,
                                      unsigned a3, unsigned b0, unsigned b1) {
    asm volatile(
        "mma.sync.aligned.m16n8k16.row.col.f32.f16.f16.f32 "
        "{%0,%1,%2,%3},{%4,%5,%6,%7},{%8,%9},{%0,%1,%2,%3};\n"
        : "+f"(d[0]), "+f"(d[1]), "+f"(d[2]), "+f"(d[3])
        : "r"(a0), "r"(a1), "r"(a2), "r"(a3), "r"(b0), "r"(b1));
}

__device__ __forceinline__ unsigned packh2(float a, float b) {
    __half2 h = __floats2half2_rn(a, b);
    unsigned r;
    memcpy(&r, &h, 4);
    return r;
}

__device__ __forceinline__ void cp16(void* smem, const void* g) {
    unsigned sa = (unsigned)__cvta_generic_to_shared(smem);
    asm volatile("cp.async.cg.shared.global [%0], [%1], 16;\n" ::"r"(sa), "l"(g));
}
#define CP_COMMIT asm volatile("cp.async.commit_group;\n" ::: "memory")
#define CP_WAIT1  asm volatile("cp.async.wait_group 1;\n" ::: "memory")

// ===================== projection =====================
__device__ __forceinline__ void proj_pass(const float* __restrict__ W,
                                          const float* __restrict__ bias,
                                          const float* __restrict__ Xs, float* Wt,
                                          float acc[4][8], int co, int px, int tid) {
    __syncthreads();
    for (int idx = tid; idx < 4096; idx += 128) {
        int o = idx >> 6, ci = idx & 63;
        Wt[ci * WSTR + o] = W[idx];  // transpose: Wt[cin][cout]
    }
    __syncthreads();
    float b0 = bias[co], b1 = bias[co + 1], b2 = bias[co + 2], b3 = bias[co + 3];
#pragma unroll
    for (int p = 0; p < 8; ++p) {
        acc[0][p] = b0; acc[1][p] = b1; acc[2][p] = b2; acc[3][p] = b3;
    }
#pragma unroll 4
    for (int ci = 0; ci < 64; ++ci) {
        float4 w = *(const float4*)&Wt[ci * WSTR + co];
        float4 xa = *(const float4*)&Xs[ci * 64 + px];
        float4 xb = *(const float4*)&Xs[ci * 64 + px + 4];
        float xs[8] = {xa.x, xa.y, xa.z, xa.w, xb.x, xb.y, xb.z, xb.w};
        float ws[4] = {w.x, w.y, w.z, w.w};
#pragma unroll
        for (int cc = 0; cc < 4; ++cc)
#pragma unroll
            for (int p = 0; p < 8; ++p) acc[cc][p] = fmaf(ws[cc], xs[p], acc[cc][p]);
    }
}

__global__ void __launch_bounds__(128)
proj_kernel(const float* __restrict__ x1, const float* __restrict__ x2,
            const float* __restrict__ wq, const float* __restrict__ bq,
            const float* __restrict__ wk, const float* __restrict__ bk,
            const float* __restrict__ wv, const float* __restrict__ bv) {
    extern __shared__ unsigned char dynsm[];
    float* Xs1 = (float*)dynsm;           // 64x64
    float* Xs2 = Xs1 + 4096;              // 64x64
    float* Wt  = Xs2 + 4096;              // 64x68

    const int b = blockIdx.y;
    const int iBase = blockIdx.x * 64;
    const int tid = threadIdx.x;

    for (int idx = tid; idx < 1024; idx += 128) {
        int r = idx >> 4, c4 = (idx & 15) << 2;
        *(float4*)&Xs1[r * 64 + c4] =
            *(const float4*)(x1 + (size_t)(b * 64 + r) * NPIX + iBase + c4);
        *(float4*)&Xs2[r * 64 + c4] =
            *(const float4*)(x2 + (size_t)(b * 64 + r) * NPIX + iBase + c4);
    }

    const int co = (tid & 15) * 4;  // 4 output channels
    const int px = (tid >> 4) * 8;  // 8 pixels
    int pc[4], pp[8];
#pragma unroll
    for (int cc = 0; cc < 4; ++cc) pc[cc] = perm64(co + cc);
#pragma unroll
    for (int p = 0; p < 8; ++p) pp[p] = perm64(px + p);

    float acc[4][8];

    // ---- q ----
    proj_pass(wq, bq, Xs1, Wt, acc, co, px, tid);
#pragma unroll
    for (int p = 0; p < 8; ++p) {
        size_t rb = ((size_t)b * NPIX + iBase + px + p) * 64;
#pragma unroll
        for (int cc = 0; cc < 4; ++cc) g_qh[rb + pc[cc]] = __float2half(acc[cc][p]);
    }
    // ---- k ----
    proj_pass(wk, bk, Xs2, Wt, acc, co, px, tid);
#pragma unroll
    for (int p = 0; p < 8; ++p) {
        size_t rb = ((size_t)b * NPIX + iBase + px + p) * 64;
#pragma unroll
        for (int cc = 0; cc < 4; ++cc) g_kh[rb + pc[cc]] = __float2half(acc[cc][p]);
    }
    // ---- v (c-major, pixel-permuted within tile) ----
    proj_pass(wv, bv, Xs2, Wt, acc, co, px, tid);
#pragma unroll
    for (int cc = 0; cc < 4; ++cc) {
        size_t rb = ((size_t)(b * 64 + co + cc)) * NPIX + iBase;
#pragma unroll
        for (int p = 0; p < 8; ++p) g_vh[rb + pp[p]] = __float2half(acc[cc][p]);
    }
}

// ===================== flash attention (fp16 mma, cp.async pipeline) =====================
__global__ void __launch_bounds__(128)
attn_kernel(const float* __restrict__ x1, const float* __restrict__ gamma_p,
            float* __restrict__ out) {
    extern __shared__ unsigned char dynsm[];
    __half* Qs  = (__half*)dynsm;
    __half* Ks0 = Qs + TILE_HALFS;
    __half* Ks1 = Ks0 + TILE_HALFS;
    __half* Vs0 = Ks1 + TILE_HALFS;
    __half* Vs1 = Vs0 + TILE_HALFS;
    float*  Ob  = (float*)dynsm;  // epilogue reuse (64*68 floats, fits in Qs+Ks0)

    const int b = blockIdx.y;
    const int iBase = blockIdx.x * 64;
    const int tid = threadIdx.x;
    const int warp = tid >> 5, lane = tid & 31;
    const int g = lane >> 2, t = lane & 3;
    const int qr = warp * 16 + g;

    const __half* gq = g_qh + ((size_t)b * NPIX + iBase) * 64;
    const __half* gk = g_kh + (size_t)b * NPIX * 64;
    const __half* gv = g_vh + (size_t)b * 64 * NPIX;

    // prologue: async-stage Q tile + K/V tile 0
    for (int idx = tid; idx < 512; idx += 128) {
        int r = idx >> 3, ch = (idx & 7) * 8;
        cp16(Qs + r * KH + ch, gq + r * 64 + ch);
        cp16(Ks0 + r * KH + ch, gk + (size_t)r * 64 + ch);
        cp16(Vs0 + r * KH + ch, gv + (size_t)r * NPIX + ch);
    }
    CP_COMMIT;

    float oAcc[8][4];
#pragma unroll
    for (int i = 0; i < 8; i++) {
        oAcc[i][0] = 0.f; oAcc[i][1] = 0.f; oAcc[i][2] = 0.f; oAcc[i][3] = 0.f;
    }
    float mA = -1e30f, mB = -1e30f, lA = 0.f, lB = 0.f;
    uint4 qa, qb, qc, qd;

    for (int jt = 0; jt < 64; ++jt) {
        __half* Kf = (jt & 1) ? Ks1 : Ks0;
        __half* Vf = (jt & 1) ? Vs1 : Vs0;
        if (jt + 1 < 64) {
            __half* Kn = (jt & 1) ? Ks0 : Ks1;
            __half* Vn = (jt & 1) ? Vs0 : Vs1;
            const __half* gkr = gk + (size_t)(jt + 1) * 64 * 64;
            const __half* gvr = gv + (size_t)(jt + 1) * 64;
            for (int idx = tid; idx < 512; idx += 128) {
                int r = idx >> 3, ch = (idx & 7) * 8;
                cp16(Kn + r * KH + ch, gkr + (size_t)r * 64 + ch);
                cp16(Vn + r * KH + ch, gvr + (size_t)r * NPIX + ch);
            }
        }
        CP_COMMIT;
        CP_WAIT1;
        __syncthreads();

        if (jt == 0) {  // Q fragments (register-resident for all 64 tiles)
            qa = *(const uint4*)&Qs[qr * KH + t * 16];
            qb = *(const uint4*)&Qs[(qr + 8) * KH + t * 16];
            qc = *(const uint4*)&Qs[qr * KH + t * 16 + 8];
            qd = *(const uint4*)&Qs[(qr + 8) * KH + t * 16 + 8];
        }

        // ---- S = Q K^T (16x64 per warp) ----
        float s[8][4];
#pragma unroll
        for (int i = 0; i < 8; i++) {
            s[i][0] = 0.f; s[i][1] = 0.f; s[i][2] = 0.f; s[i][3] = 0.f;
        }
#pragma unroll
        for (int tn = 0; tn < 8; ++tn) {
            const uint4 k0 = *(const uint4*)&Kf[(tn * 8 + g) * KH + t * 16];
            const uint4 k1 = *(const uint4*)&Kf[(tn * 8 + g) * KH + t * 16 + 8];
            mma16(s[tn], qa.x, qb.x, qa.y, qb.y, k0.x, k0.y);
            mma16(s[tn], qa.z, qb.z, qa.w, qb.w, k0.z, k0.w);
            mma16(s[tn], qc.x, qd.x, qc.y, qd.y, k1.x, k1.y);
            mma16(s[tn], qc.z, qd.z, qc.w, qd.w, k1.z, k1.w);
        }

        // ---- online softmax (rows qr / qr+8) ----
        float tmA = -1e30f, tmB = -1e30f;
#pragma unroll
        for (int tn = 0; tn < 8; ++tn) {
            tmA = fmaxf(tmA, fmaxf(s[tn][0], s[tn][1]));
            tmB = fmaxf(tmB, fmaxf(s[tn][2], s[tn][3]));
        }
        tmA = fmaxf(tmA, __shfl_xor_sync(0xffffffffu, tmA, 1));
        tmA = fmaxf(tmA, __shfl_xor_sync(0xffffffffu, tmA, 2));
        tmB = fmaxf(tmB, __shfl_xor_sync(0xffffffffu, tmB, 1));
        tmB = fmaxf(tmB, __shfl_xor_sync(0xffffffffu, tmB, 2));
        const float mAn = fmaxf(mA, tmA), mBn = fmaxf(mB, tmB);
        const float scA = __expf(mA - mAn), scB = __expf(mB - mBn);
        mA = mAn; mB = mBn;
        float sumA = 0.f, sumB = 0.f;
#pragma unroll
        for (int tn = 0; tn < 8; ++tn) {
            s[tn][0] = __expf(s[tn][0] - mA);
            s[tn][1] = __expf(s[tn][1] - mA);
            s[tn][2] = __expf(s[tn][2] - mB);
            s[tn][3] = __expf(s[tn][3] - mB);
            sumA += s[tn][0] + s[tn][1];
            sumB += s[tn][2] + s[tn][3];
            oAcc[tn][0] *= scA; oAcc[tn][1] *= scA;
            oAcc[tn][2] *= scB; oAcc[tn][3] *= scB;
        }
        sumA += __shfl_xor_sync(0xffffffffu, sumA, 1);
        sumA += __shfl_xor_sync(0xffffffffu, sumA, 2);
        sumB += __shfl_xor_sync(0xffffffffu, sumB, 1);
        sumB += __shfl_xor_sync(0xffffffffu, sumB, 2);
        lA = lA * scA + sumA;
        lB = lB * scB + sumB;

        // ---- P packed directly into A-fragments (no smem round-trip) ----
        unsigned pa[4][4];
#pragma unroll
        for (int kj = 0; kj < 4; ++kj) {
            pa[kj][0] = packh2(s[2 * kj][0], s[2 * kj][1]);
            pa[kj][1] = packh2(s[2 * kj][2], s[2 * kj][3]);
            pa[kj][2] = packh2(s[2 * kj + 1][0], s[2 * kj + 1][1]);
            pa[kj][3] = packh2(s[2 * kj + 1][2], s[2 * kj + 1][3]);
        }

        // ---- O += P V ----
#pragma unroll
        for (int tn = 0; tn < 8; ++tn) {
            const uint4 v0 = *(const uint4*)&Vf[(tn * 8 + g) * KH + t * 16];
            const uint4 v1 = *(const uint4*)&Vf[(tn * 8 + g) * KH + t * 16 + 8];
            mma16(oAcc[tn], pa[0][0], pa[0][1], pa[0][2], pa[0][3], v0.x, v0.y);
            mma16(oAcc[tn], pa[1][0], pa[1][1], pa[1][2], pa[1][3], v0.z, v0.w);
            mma16(oAcc[tn], pa[2][0], pa[2][1], pa[2][2], pa[2][3], v1.x, v1.y);
            mma16(oAcc[tn], pa[3][0], pa[3][1], pa[3][2], pa[3][3], v1.z, v1.w);
        }
        __syncthreads();
    }

    // ---- epilogue: normalize, transpose via smem, coalesced gamma*O + x1 ----
    const float invA = 1.0f / lA;
    const float invB = 1.0f / lB;
#pragma unroll
    for (int tn = 0; tn < 8; ++tn) {
        int c0 = tn * 8 + 2 * t;
        Ob[c0 * 68 + qr]           = oAcc[tn][0] * invA;
        Ob[(c0 + 1) * 68 + qr]     = oAcc[tn][1] * invA;
        Ob[c0 * 68 + qr + 8]       = oAcc[tn][2] * invB;
        Ob[(c0 + 1) * 68 + qr + 8] = oAcc[tn][3] * invB;
    }
    __syncthreads();
    const float gm = gamma_p[0];
    for (int idx = tid; idx < 1024; idx += 128) {
        int c = idx >> 4, i4 = (idx & 15) * 4;
        size_t gi = ((size_t)(b * 64 + c)) * NPIX + iBase + i4;
        float4 xv = *(const float4*)(x1 + gi);
        float4 ov = *(const float4*)&Ob[c * 68 + i4];
        float4 r;
        r.x = gm * ov.x + xv.x;
        r.y = gm * ov.y + xv.y;
        r.z = gm * ov.z + xv.z;
        r.w = gm * ov.w + xv.w;
        *(float4*)(out + gi) = r;
    }
}

// ===================== launch =====================
extern "C" void kernel_launch(void* const* d_in, const int* in_sizes, int n_in,
                              void* d_out, int out_size) {
    const float* x1 = (const float*)d_in[0];
    const float* x2 = (const float*)d_in[1];
    const float* wq = (const float*)d_in[2];
    const float* bq = (const float*)d_in[3];
    const float* wk = (const float*)d_in[4];
    const float* bk = (const float*)d_in[5];
    const float* wv = (const float*)d_in[6];
    const float* bv = (const float*)d_in[7];
    const float* gamma = (const float*)d_in[8];
    float* out = (float*)d_out;

    const int proj_smem = (4096 + 4096 + 64 * WSTR) * (int)sizeof(float);  // 50176
    const int attn_smem = 5 * TILE_HALFS * (int)sizeof(__half);            // 46080
    cudaFuncSetAttribute(proj_kernel, cudaFuncAttributeMaxDynamicSharedMemorySize,
                         proj_smem);
    cudaFuncSetAttribute(attn_kernel, cudaFuncAttributeMaxDynamicSharedMemorySize,
                         attn_smem);

    dim3 grid(NPIX / 64, 4);
    proj_kernel<<<grid, 128, proj_smem>>>(x1, x2, wq, bq, wk, bk, wv, bv);
    attn_kernel<<<grid, 128, attn_smem>>>(x1, gamma, out);
}

// round 16
// speedup vs baseline: 3.0299x; 1.0147x over previous
#include <cuda_runtime.h>
#include <cuda_fp16.h>

#define NPIX 4096
#define KH   72                      // half-stride of fragment tiles (144B = 9*16B -> conflict-free)
#define TILE_HALFS (64 * KH)         // 4608 halves
#define WSTR 68                      // proj Wt float stride

// -------- device-global scratch (allocation-free) --------
__device__ __half g_qh[4ull * NPIX * 64];   // [b][n][perm(c)]
__device__ __half g_kh[4ull * NPIX * 64];   // [b][n][perm(c)]
__device__ __half g_vh[4ull * 64 * NPIX];   // [b][c][tile*64 + perm(j_local)]

// fragment permutation: c = kk*16 + 8h + 2t + e  ->  p = t*16 + kk*4 + h*2 + e
__device__ __forceinline__ int perm64(int c) {
    return ((c >> 1) & 3) * 16 + (c >> 4) * 4 + ((c >> 3) & 1) * 2 + (c & 1);
}

// D += A(16x16 f16) * B(16x8 f16), fp32 accum
__device__ __forceinline__ void mma16(float* d, unsigned a0, unsigned a1, unsigned a2,
                                      unsigned a3, unsigned b0, unsigned b1) {
    asm volatile(
        "mma.sync.aligned.m16n8k16.row.col.f32.f16.f16.f32 "
        "{%0,%1,%2,%3},{%4,%5,%6,%7},{%8,%9},{%0,%1,%2,%3};\n"
        : "+f"(d[0]), "+f"(d[1]), "+f"(d[2]), "+f"(d[3])
        : "r"(a0), "r"(a1), "r"(a2), "r"(a3), "r"(b0), "r"(b1));
}

__device__ __forceinline__ unsigned packh2(float a, float b) {
    __half2 h = __floats2half2_rn(a, b);
    unsigned r;
    memcpy(&r, &h, 4);
    return r;
}

__device__ __forceinline__ void cp16(void* smem, const void* g) {
    unsigned sa = (unsigned)__cvta_generic_to_shared(smem);
    asm volatile("cp.async.cg.shared.global [%0], [%1], 16;\n" ::"r"(sa), "l"(g));
}
#define CP_COMMIT asm volatile("cp.async.commit_group;\n" ::: "memory")
#define CP_WAIT1  asm volatile("cp.async.wait_group 1;\n" ::: "memory")

// ===================== projection =====================
__device__ __forceinline__ void proj_pass(const float* __restrict__ W,
                                          const float* __restrict__ bias,
                                          const float* __restrict__ Xs, float* Wt,
                                          float acc[4][8], int co, int px, int tid) {
    __syncthreads();
    for (int idx = tid; idx < 4096; idx += 128) {
        int o = idx >> 6, ci = idx & 63;
        Wt[ci * WSTR + o] = W[idx];  // transpose: Wt[cin][cout]
    }
    __syncthreads();
    float b0 = bias[co], b1 = bias[co + 1], b2 = bias[co + 2], b3 = bias[co + 3];
#pragma unroll
    for (int p = 0; p < 8; ++p) {
        acc[0][p] = b0; acc[1][p] = b1; acc[2][p] = b2; acc[3][p] = b3;
    }
#pragma unroll 4
    for (int ci = 0; ci < 64; ++ci) {
        float4 w = *(const float4*)&Wt[ci * WSTR + co];
        float4 xa = *(const float4*)&Xs[ci * 64 + px];
        float4 xb = *(const float4*)&Xs[ci * 64 + px + 4];
        float xs[8] = {xa.x, xa.y, xa.z, xa.w, xb.x, xb.y, xb.z, xb.w};
        float ws[4] = {w.x, w.y, w.z, w.w};
#pragma unroll
        for (int cc = 0; cc < 4; ++cc)
#pragma unroll
            for (int p = 0; p < 8; ++p) acc[cc][p] = fmaf(ws[cc], xs[p], acc[cc][p]);
    }
}

__global__ void __launch_bounds__(128)
proj_kernel(const float* __restrict__ x1, const float* __restrict__ x2,
            const float* __restrict__ wq, const float* __restrict__ bq,
            const float* __restrict__ wk, const float* __restrict__ bk,
            const float* __restrict__ wv, const float* __restrict__ bv) {
    extern __shared__ unsigned char dynsm[];
    float* Xs1 = (float*)dynsm;           // 64x64
    float* Xs2 = Xs1 + 4096;              // 64x64
    float* Wt  = Xs2 + 4096;              // 64x68

    const int b = blockIdx.y;
    const int iBase = blockIdx.x * 64;
    const int tid = threadIdx.x;

    for (int idx = tid; idx < 1024; idx += 128) {
        int r = idx >> 4, c4 = (idx & 15) << 2;
        *(float4*)&Xs1[r * 64 + c4] =
            *(const float4*)(x1 + (size_t)(b * 64 + r) * NPIX + iBase + c4);
        *(float4*)&Xs2[r * 64 + c4] =
            *(const float4*)(x2 + (size_t)(b * 64 + r) * NPIX + iBase + c4);
    }

    const int co = (tid & 15) * 4;  // 4 output channels
    const int px = (tid >> 4) * 8;  // 8 pixels
    int pc[4], pp[8];
#pragma unroll
    for (int cc = 0; cc < 4; ++cc) pc[cc] = perm64(co + cc);
#pragma unroll
    for (int p = 0; p < 8; ++p) pp[p] = perm64(px + p);

    float acc[4][8];

    // ---- q ----
    proj_pass(wq, bq, Xs1, Wt, acc, co, px, tid);
#pragma unroll
    for (int p = 0; p < 8; ++p) {
        size_t rb = ((size_t)b * NPIX + iBase + px + p) * 64;
#pragma unroll
        for (int cc = 0; cc < 4; ++cc) g_qh[rb + pc[cc]] = __float2half(acc[cc][p]);
    }
    // ---- k ----
    proj_pass(wk, bk, Xs2, Wt, acc, co, px, tid);
#pragma unroll
    for (int p = 0; p < 8; ++p) {
        size_t rb = ((size_t)b * NPIX + iBase + px + p) * 64;
#pragma unroll
        for (int cc = 0; cc < 4; ++cc) g_kh[rb + pc[cc]] = __float2half(acc[cc][p]);
    }
    // ---- v (c-major, pixel-permuted within tile) ----
    proj_pass(wv, bv, Xs2, Wt, acc, co, px, tid);
#pragma unroll
    for (int cc = 0; cc < 4; ++cc) {
        size_t rb = ((size_t)(b * 64 + co + cc)) * NPIX + iBase;
#pragma unroll
        for (int p = 0; p < 8; ++p) g_vh[rb + pp[p]] = __float2half(acc[cc][p]);
    }
}

// ===================== flash attention (fp16 mma, cp.async pipeline) =====================
__global__ void __launch_bounds__(128)
attn_kernel(const float* __restrict__ x1, const float* __restrict__ gamma_p,
            float* __restrict__ out) {
    extern __shared__ unsigned char dynsm[];
    __half* Qs  = (__half*)dynsm;
    __half* Ks0 = Qs + TILE_HALFS;
    __half* Ks1 = Ks0 + TILE_HALFS;
    __half* Vs0 = Ks1 + TILE_HALFS;
    __half* Vs1 = Vs0 + TILE_HALFS;
    float*  Ob  = (float*)dynsm;  // epilogue reuse (64*68 floats, fits in Qs+Ks0)

    const int b = blockIdx.y;
    const int iBase = blockIdx.x * 64;
    const int tid = threadIdx.x;
    const int warp = tid >> 5, lane = tid & 31;
    const int g = lane >> 2, t = lane & 3;
    const int qr = warp * 16 + g;

    const __half* gq = g_qh + ((size_t)b * NPIX + iBase) * 64;
    const __half* gk = g_kh + (size_t)b * NPIX * 64;
    const __half* gv = g_vh + (size_t)b * 64 * NPIX;

    // prologue: async-stage Q tile + K/V tile 0
    for (int idx = tid; idx < 512; idx += 128) {
        int r = idx >> 3, ch = (idx & 7) * 8;
        cp16(Qs + r * KH + ch, gq + r * 64 + ch);
        cp16(Ks0 + r * KH + ch, gk + (size_t)r * 64 + ch);
        cp16(Vs0 + r * KH + ch, gv + (size_t)r * NPIX + ch);
    }
    CP_COMMIT;

    float oAcc[8][4];
#pragma unroll
    for (int i = 0; i < 8; i++) {
        oAcc[i][0] = 0.f; oAcc[i][1] = 0.f; oAcc[i][2] = 0.f; oAcc[i][3] = 0.f;
    }
    float mA = -1e30f, mB = -1e30f, lA = 0.f, lB = 0.f;
    uint4 qa, qb, qc, qd;

    for (int jt = 0; jt < 64; ++jt) {
        __half* Kf = (jt & 1) ? Ks1 : Ks0;
        __half* Vf = (jt & 1) ? Vs1 : Vs0;
        if (jt + 1 < 64) {
            __half* Kn = (jt & 1) ? Ks0 : Ks1;
            __half* Vn = (jt & 1) ? Vs0 : Vs1;
            const __half* gkr = gk + (size_t)(jt + 1) * 64 * 64;
            const __half* gvr = gv + (size_t)(jt + 1) * 64;
            for (int idx = tid; idx < 512; idx += 128) {
                int r = idx >> 3, ch = (idx & 7) * 8;
                cp16(Kn + r * KH + ch, gkr + (size_t)r * 64 + ch);
                cp16(Vn + r * KH + ch, gvr + (size_t)r * NPIX + ch);
            }
        }
        CP_COMMIT;
        CP_WAIT1;
        __syncthreads();

        if (jt == 0) {  // Q fragments (register-resident for all 64 tiles)
            qa = *(const uint4*)&Qs[qr * KH + t * 16];
            qb = *(const uint4*)&Qs[(qr + 8) * KH + t * 16];
            qc = *(const uint4*)&Qs[qr * KH + t * 16 + 8];
            qd = *(const uint4*)&Qs[(qr + 8) * KH + t * 16 + 8];
        }

        // ---- S = Q K^T (16x64 per warp) ----
        float s[8][4];
#pragma unroll
        for (int i = 0; i < 8; i++) {
            s[i][0] = 0.f; s[i][1] = 0.f; s[i][2] = 0.f; s[i][3] = 0.f;
        }
#pragma unroll
        for (int tn = 0; tn < 8; ++tn) {
            const uint4 k0 = *(const uint4*)&Kf[(tn * 8 + g) * KH + t * 16];
            const uint4 k1 = *(const uint4*)&Kf[(tn * 8 + g) * KH + t * 16 + 8];
            mma16(s[tn], qa.x, qb.x, qa.y, qb.y, k0.x, k0.y);
            mma16(s[tn], qa.z, qb.z, qa.w, qb.w, k0.z, k0.w);
            mma16(s[tn], qc.x, qd.x, qc.y, qd.y, k1.x, k1.y);
            mma16(s[tn], qc.z, qd.z, qc.w, qd.w, k1.z, k1.w);
        }

        // ---- online softmax (rows qr / qr+8) ----
        float tmA = -1e30f, tmB = -1e30f;
#pragma unroll
        for (int tn = 0; tn < 8; ++tn) {
            tmA = fmaxf(tmA, fmaxf(s[tn][0], s[tn][1]));
            tmB = fmaxf(tmB, fmaxf(s[tn][2], s[tn][3]));
        }
        tmA = fmaxf(tmA, __shfl_xor_sync(0xffffffffu, tmA, 1));
        tmA = fmaxf(tmA, __shfl_xor_sync(0xffffffffu, tmA, 2));
        tmB = fmaxf(tmB, __shfl_xor_sync(0xffffffffu, tmB, 1));
        tmB = fmaxf(tmB, __shfl_xor_sync(0xffffffffu, tmB, 2));
        const float mAn = fmaxf(mA, tmA), mBn = fmaxf(mB, tmB);
        const float scA = __expf(mA - mAn), scB = __expf(mB - mBn);
        mA = mAn; mB = mBn;
        float sumA = 0.f, sumB = 0.f;
#pragma unroll
        for (int tn = 0; tn < 8; ++tn) {
            s[tn][0] = __expf(s[tn][0] - mA);
            s[tn][1] = __expf(s[tn][1] - mA);
            s[tn][2] = __expf(s[tn][2] - mB);
            s[tn][3] = __expf(s[tn][3] - mB);
            sumA += s[tn][0] + s[tn][1];
            sumB += s[tn][2] + s[tn][3];
            oAcc[tn][0] *= scA; oAcc[tn][1] *= scA;
            oAcc[tn][2] *= scB; oAcc[tn][3] *= scB;
        }
        sumA += __shfl_xor_sync(0xffffffffu, sumA, 1);
        sumA += __shfl_xor_sync(0xffffffffu, sumA, 2);
        sumB += __shfl_xor_sync(0xffffffffu, sumB, 1);
        sumB += __shfl_xor_sync(0xffffffffu, sumB, 2);
        lA = lA * scA + sumA;
        lB = lB * scB + sumB;

        // ---- P packed directly into A-fragments (no smem round-trip) ----
        unsigned pa[4][4];
#pragma unroll
        for (int kj = 0; kj < 4; ++kj) {
            pa[kj][0] = packh2(s[2 * kj][0], s[2 * kj][1]);
            pa[kj][1] = packh2(s[2 * kj][2], s[2 * kj][3]);
            pa[kj][2] = packh2(s[2 * kj + 1][0], s[2 * kj + 1][1]);
            pa[kj][3] = packh2(s[2 * kj + 1][2], s[2 * kj + 1][3]);
        }

        // ---- O += P V ----
#pragma unroll
        for (int tn = 0; tn < 8; ++tn) {
            const uint4 v0 = *(const uint4*)&Vf[(tn * 8 + g) * KH + t * 16];
            const uint4 v1 = *(const uint4*)&Vf[(tn * 8 + g) * KH + t * 16 + 8];
            mma16(oAcc[tn], pa[0][0], pa[0][1], pa[0][2], pa[0][3], v0.x, v0.y);
            mma16(oAcc[tn], pa[1][0], pa[1][1], pa[1][2], pa[1][3], v0.z, v0.w);
            mma16(oAcc[tn], pa[2][0], pa[2][1], pa[2][2], pa[2][3], v1.x, v1.y);
            mma16(oAcc[tn], pa[3][0], pa[3][1], pa[3][2], pa[3][3], v1.z, v1.w);
        }
        __syncthreads();
    }

    // ---- epilogue: normalize, transpose via smem, coalesced gamma*O + x1 ----
    const float invA = 1.0f / lA;
    const float invB = 1.0f / lB;
#pragma unroll
    for (int tn = 0; tn < 8; ++tn) {
        int c0 = tn * 8 + 2 * t;
        Ob[c0 * 68 + qr]           = oAcc[tn][0] * invA;
        Ob[(c0 + 1) * 68 + qr]     = oAcc[tn][1] * invA;
        Ob[c0 * 68 + qr + 8]       = oAcc[tn][2] * invB;
        Ob[(c0 + 1) * 68 + qr + 8] = oAcc[tn][3] * invB;
    }
    __syncthreads();
    const float gm = gamma_p[0];
    for (int idx = tid; idx < 1024; idx += 128) {
        int c = idx >> 4, i4 = (idx & 15) * 4;
        size_t gi = ((size_t)(b * 64 + c)) * NPIX + iBase + i4;
        float4 xv = *(const float4*)(x1 + gi);
        float4 ov = *(const float4*)&Ob[c * 68 + i4];
        float4 r;
        r.x = gm * ov.x + xv.x;
        r.y = gm * ov.y + xv.y;
        r.z = gm * ov.z + xv.z;
        r.w = gm * ov.w + xv.w;
        *(float4*)(out + gi) = r;
    }
}

// ===================== launch =====================
extern "C" void kernel_launch(void* const* d_in, const int* in_sizes, int n_in,
                              void* d_out, int out_size) {
    const float* x1 = (const float*)d_in[0];
    const float* x2 = (const float*)d_in[1];
    const float* wq = (const float*)d_in[2];
    const float* bq = (const float*)d_in[3];
    const float* wk = (const float*)d_in[4];
    const float* bk = (const float*)d_in[5];
    const float* wv = (const float*)d_in[6];
    const float* bv = (const float*)d_in[7];
    const float* gamma = (const float*)d_in[8];
    float* out = (float*)d_out;

    const int proj_smem = (4096 + 4096 + 64 * WSTR) * (int)sizeof(float);  // 50176
    const int attn_smem = 5 * TILE_HALFS * (int)sizeof(__half);            // 46080
    cudaFuncSetAttribute(proj_kernel, cudaFuncAttributeMaxDynamicSharedMemorySize,
                         proj_smem);
    cudaFuncSetAttribute(attn_kernel, cudaFuncAttributeMaxDynamicSharedMemorySize,
                         attn_smem);

    dim3 grid(NPIX / 64, 4);
    proj_kernel<<<grid, 128, proj_smem>>>(x1, x2, wq, bq, wk, bk, wv, bv);
    attn_kernel<<<grid, 128, attn_smem>>>(x1, gamma, out);
}